// round 11
// baseline (speedup 1.0000x reference)
#include <cuda_runtime.h>
#include <cstdint>

typedef unsigned int u32;
typedef unsigned long long ull;

#define B_SZ 16384
#define E_SZ 256
#define V_SZ 512
#define T_MAX 16
#define PAD 66

// ---------------- persistent scratch (static device globals; no allocation) ----------
__device__ float g_h[B_SZ * E_SZ];          // GRU state [B,256]
__device__ float g_gates[B_SZ * 1024];      // [ (i_r+h_r)(256) | (i_z+h_z)(256) | i_n(256) | h_n(256) ]
__device__ float g_logits[B_SZ * V_SZ];
__device__ int   g_tok[B_SZ];
__device__ int   g_alive[B_SZ];
__device__ int   g_N[B_SZ];
__device__ float g_logp[B_SZ];

// ---------------- f32x2 helpers ----------------
__device__ __forceinline__ void fma2(ull &acc, ull a, ull b) {
    asm("fma.rn.f32x2 %0, %1, %2, %0;" : "+l"(acc) : "l"(a), "l"(b));
}
__device__ __forceinline__ void lds_v2(ull &x, ull &y, const float2 *p) {
    u32 a = (u32)__cvta_generic_to_shared(p);
    asm volatile("ld.shared.v2.u64 {%0,%1}, [%2];" : "=l"(x), "=l"(y) : "r"(a));
}
__device__ __forceinline__ float2 unpack2(ull v) {
    float2 r;
    asm("mov.b64 {%0,%1}, %2;" : "=f"(r.x), "=f"(r.y) : "l"(v));
    return r;
}

// ---------------- init: h = h1_emb[actions]; reset sieve state ----------------
__global__ void __launch_bounds__(256) init_k(const int *__restrict__ actions,
                                              const float *__restrict__ h1) {
    int idx = blockIdx.x * 256 + threadIdx.x;        // B*E threads
    int b = idx >> 8, j = idx & 255;
    g_h[idx] = h1[actions[b] * 256 + j];
    if (idx < B_SZ) {
        g_tok[idx] = 0; g_alive[idx] = 1; g_N[idx] = T_MAX; g_logp[idx] = 0.0f;
    }
}

// ---------------- GEMM (64x64 tile, BK=32, f32x2 along K) ----------------
// kind==0 (gates), grid (256,16):
//   by in [0,8):   rz region, out cols [0,512),   K=512 concat[x|h], W=[W_ih rows|W_hh rows]
//   by in [8,12):  i_n,       out cols [512,768), K=256 (x), W_ih rows 512..767
//   by in [12,16): h_n,       out cols [768,1024),K=256 (h), W_hh rows 512..767
// kind==1 (logits), grid (256,8): out g_logits, K=256 (h), W_out
__global__ void __launch_bounds__(256) gemm_k(
    const float *__restrict__ d2e, const float *__restrict__ Wih,
    const float *__restrict__ Whh, const float *__restrict__ Wout,
    const float *__restrict__ bih, const float *__restrict__ bhh,
    const float *__restrict__ bout, int kind)
{
    __shared__ __align__(16) float2 As[16 * PAD];
    __shared__ __align__(16) float2 Ws[16 * PAD];
    __shared__ int stok[64];

    const int m0 = blockIdx.x * 64;
    const int by = blockIdx.y;
    const int tid = threadIdx.x;

    int wbase, ocbase, K, ow, asrc;
    float *outp;
    if (kind == 0) {
        ow = 1024; outp = g_gates;
        if (by < 8)       { asrc = 0; wbase = by * 64;              ocbase = wbase;       K = 512; }
        else if (by < 12) { asrc = 1; wbase = 512 + (by - 8) * 64;  ocbase = wbase;       K = 256; }
        else              { asrc = 2; wbase = 512 + (by - 12) * 64; ocbase = 256 + wbase; K = 256; }
    } else {
        ow = V_SZ; outp = g_logits; asrc = 2; wbase = by * 64; ocbase = wbase; K = 256;
    }

    if (asrc <= 1 && tid < 64) stok[tid] = g_tok[m0 + tid];
    __syncthreads();

    const int wid = tid >> 5, lane = tid & 31;
    const int ty = ((wid & 3) << 2) | (lane >> 3);   // 0..15 (4 per warp)
    const int tx = ((wid >> 2) << 3) | (lane & 7);   // 0..15 (8 per warp)

    ull acc[16];
#pragma unroll
    for (int i = 0; i < 16; i++) acc[i] = 0ull;

    for (int kt = 0; kt < K; kt += 32) {
        const bool ax   = (asrc == 1) || (asrc == 0 && kt < 256);
        const int  koff = (asrc == 0 && kt >= 256) ? (kt - 256) : kt;
        const float *Wp;
        if (kind == 1)       Wp = Wout;
        else if (asrc == 1)  Wp = Wih;
        else if (asrc == 2)  Wp = Whh;
        else                 Wp = (kt < 256) ? Wih : Whh;

#pragma unroll
        for (int r = 0; r < 4; r++) {
            int e = tid + r * 256;
            int m = e >> 4, kk = e & 15;
            int k = koff + 2 * kk;
            float2 va;
            if (ax) va = *(const float2 *)(d2e + stok[m] * 256 + k);
            else    va = *(const float2 *)(g_h + (m0 + m) * 256 + k);
            As[kk * PAD + m] = va;
            Ws[kk * PAD + m] = *(const float2 *)(Wp + (wbase + m) * 256 + k);
        }
        __syncthreads();

#pragma unroll
        for (int kk = 0; kk < 16; kk++) {
            ull a0, a1, a2, a3, w0, w1, w2, w3;
            lds_v2(a0, a1, &As[kk * PAD + ty * 4]);
            lds_v2(a2, a3, &As[kk * PAD + ty * 4 + 2]);
            lds_v2(w0, w1, &Ws[kk * PAD + tx * 4]);
            lds_v2(w2, w3, &Ws[kk * PAD + tx * 4 + 2]);
            fma2(acc[0],  a0, w0); fma2(acc[1],  a0, w1); fma2(acc[2],  a0, w2); fma2(acc[3],  a0, w3);
            fma2(acc[4],  a1, w0); fma2(acc[5],  a1, w1); fma2(acc[6],  a1, w2); fma2(acc[7],  a1, w3);
            fma2(acc[8],  a2, w0); fma2(acc[9],  a2, w1); fma2(acc[10], a2, w2); fma2(acc[11], a2, w3);
            fma2(acc[12], a3, w0); fma2(acc[13], a3, w1); fma2(acc[14], a3, w2); fma2(acc[15], a3, w3);
        }
        __syncthreads();
    }

#pragma unroll
    for (int i = 0; i < 4; i++) {
        int row = m0 + ty * 4 + i;
        float v[4];
#pragma unroll
        for (int j = 0; j < 4; j++) {
            float2 s = unpack2(acc[i * 4 + j]);
            int n = tx * 4 + j;
            float bb;
            if (kind == 1)     bb = bout[wbase + n];
            else if (by < 8)   bb = bih[wbase + n] + bhh[wbase + n];
            else if (by < 12)  bb = bih[wbase + n];
            else               bb = bhh[wbase + n];
            v[j] = s.x + s.y + bb;
        }
        *(float4 *)(outp + row * ow + ocbase + tx * 4) = make_float4(v[0], v[1], v[2], v[3]);
    }
}

// ---------------- pointwise GRU combine ----------------
__global__ void __launch_bounds__(256) gru_k() {
    int idx = blockIdx.x * 256 + threadIdx.x;        // B*E threads
    const float *g = g_gates + (idx >> 8) * 1024;
    int j = idx & 255;
    float pr = g[j], pz = g[256 + j], pn = g[512 + j], hn = g[768 + j];
    // XLA logistic expander: logistic(x) = 0.5 + 0.5*tanh(0.5*x)
    float r = 0.5f + 0.5f * tanhf(0.5f * pr);
    float z = 0.5f + 0.5f * tanhf(0.5f * pz);
    float n = tanhf(fmaf(r, hn, pn));
    float h = g_h[idx];
    g_h[idx] = (1.0f - z) * n + z * h;
}

// ---------------- threefry2x32, ctr=(0, c); returns x0 ^ x1 (partitionable bits) ----
__device__ __forceinline__ u32 tf_bits(u32 k0, u32 k1, u32 ctr) {
    u32 ks2 = k0 ^ k1 ^ 0x1BD11BDAu;
    u32 x0 = k0;               // 0 + k0
    u32 x1 = ctr + k1;
#define TFR(r) { x0 += x1; x1 = __funnelshift_l(x1, x1, r); x1 ^= x0; }
    TFR(13) TFR(15) TFR(26) TFR(6)
    x0 += k1;  x1 += ks2 + 1u;
    TFR(17) TFR(29) TFR(16) TFR(24)
    x0 += ks2; x1 += k0 + 2u;
    TFR(13) TFR(15) TFR(26) TFR(6)
    x0 += k0;  x1 += k1 + 3u;
    TFR(17) TFR(29) TFR(16) TFR(24)
    x0 += k1;  x1 += ks2 + 4u;
    TFR(13) TFR(15) TFR(26) TFR(6)
    x0 += ks2; x1 += k0 + 5u;
#undef TFR
    return x0 ^ x1;
}

// ---------------- sampler: one warp per row ----------------
__global__ void __launch_bounds__(256) sample_k(float *__restrict__ d_out,
                                                int t, u32 k0, u32 k1) {
    int row  = blockIdx.x * 8 + (threadIdx.x >> 5);
    int lane = threadIdx.x & 31;
    const float *lrow = g_logits + row * V_SZ;
    u32 cbase = (u32)row * V_SZ + (u32)lane;

    float best = -1e38f, blog = 0.0f, mx = -1e38f;
    int bidx = 0;
#pragma unroll 1
    for (int c = 0; c < 16; c++) {
        int v = lane + 32 * c;                       // ascending v per lane
        float lg = lrow[v];
        mx = fmaxf(mx, lg);
        u32 bits = tf_bits(k0, k1, cbase + 32u * c);
        float fl = __uint_as_float((bits >> 9) | 0x3f800000u) - 1.0f;
        float u  = fl + 1.17549435e-38f;             // uniform in [tiny, 1)
        float gv = -logf(-logf(u));                  // gumbel
        float s  = gv + lg;
        if (s > best) { best = s; bidx = v; blog = lg; }   // strict > keeps lowest v
    }
    // max logit
    for (int o = 16; o; o >>= 1) mx = fmaxf(mx, __shfl_xor_sync(0xffffffffu, mx, o));
    // sum of exp(shifted)
    float se = 0.0f;
#pragma unroll 1
    for (int c = 0; c < 16; c++) se += expf(lrow[lane + 32 * c] - mx);
    for (int o = 16; o; o >>= 1) se += __shfl_xor_sync(0xffffffffu, se, o);
    // lexicographic argmax reduce (score desc, index asc)
    for (int o = 16; o; o >>= 1) {
        float s2 = __shfl_xor_sync(0xffffffffu, best, o);
        int   i2 = __shfl_xor_sync(0xffffffffu, bidx, o);
        float l2 = __shfl_xor_sync(0xffffffffu, blog, o);
        if (s2 > best || (s2 == best && i2 < bidx)) { best = s2; bidx = i2; blog = l2; }
    }
    if (lane == 0) {
        int alive = g_alive[row];
        float lp = (blog - mx) - logf(se);
        float logp = g_logp[row] + (alive ? lp : 0.0f);
        int tok = alive ? bidx : 0;
        if (alive && tok == 0) g_N[row] = t + 1;     // newly dead
        g_alive[row] = (alive && tok != 0) ? 1 : 0;
        g_logp[row]  = logp;
        g_tok[row]   = tok;
        d_out[row * T_MAX + t] = (float)tok;
        if (t == T_MAX - 1) {
            d_out[B_SZ * T_MAX + row]       = (float)g_N[row];
            d_out[B_SZ * (T_MAX + 1) + row] = logp;
        }
    }
}

// ---------------- host threefry (step keys) ----------------
static void host_tf(u32 k0, u32 k1, u32 c0, u32 c1, u32 &o0, u32 &o1) {
    u32 ks2 = k0 ^ k1 ^ 0x1BD11BDAu;
    u32 x0 = c0 + k0, x1 = c1 + k1;
#define HR(r) { x0 += x1; x1 = (x1 << (r)) | (x1 >> (32 - (r))); x1 ^= x0; }
    HR(13) HR(15) HR(26) HR(6)
    x0 += k1;  x1 += ks2 + 1u;
    HR(17) HR(29) HR(16) HR(24)
    x0 += ks2; x1 += k0 + 2u;
    HR(13) HR(15) HR(26) HR(6)
    x0 += k0;  x1 += k1 + 3u;
    HR(17) HR(29) HR(16) HR(24)
    x0 += k1;  x1 += ks2 + 4u;
    HR(13) HR(15) HR(26) HR(6)
    x0 += ks2; x1 += k0 + 5u;
#undef HR
    o0 = x0; o1 = x1;
}

extern "C" void kernel_launch(void* const* d_in, const int* in_sizes, int n_in,
                              void* d_out, int out_size) {
    (void)in_sizes; (void)n_in; (void)out_size;
    const int*   actions = (const int*)  d_in[0];
    // d_in[1] = global_idxes (unused by the math)
    const float* h1      = (const float*)d_in[2];
    const float* d2e     = (const float*)d_in[3];
    const float* Wih     = (const float*)d_in[4];
    const float* Whh     = (const float*)d_in[5];
    const float* bih     = (const float*)d_in[6];
    const float* bhh     = (const float*)d_in[7];
    const float* Wout    = (const float*)d_in[8];
    const float* bout    = (const float*)d_in[9];
    float* out = (float*)d_out;

    // keys[t] = threefry_block(key(0,42), (0, t))  — foldlike split of jax.random.key(42)
    u32 ks0[T_MAX], ks1[T_MAX];
    for (int t = 0; t < T_MAX; t++) host_tf(0u, 42u, 0u, (u32)t, ks0[t], ks1[t]);

    init_k<<<(B_SZ * E_SZ) / 256, 256>>>(actions, h1);
    for (int t = 0; t < T_MAX; t++) {
        gemm_k<<<dim3(B_SZ / 64, 16), 256>>>(d2e, Wih, Whh, Wout, bih, bhh, bout, 0);
        gru_k<<<(B_SZ * E_SZ) / 256, 256>>>();
        gemm_k<<<dim3(B_SZ / 64, 8), 256>>>(d2e, Wih, Whh, Wout, bih, bhh, bout, 1);
        sample_k<<<B_SZ / 8, 256>>>(out, t, ks0[t], ks1[t]);
    }
}

// round 13
// speedup vs baseline: 1.1311x; 1.1311x over previous
#include <cuda_runtime.h>
#include <cstdint>

typedef unsigned int u32;
typedef unsigned long long ull;

#define B_SZ 16384
#define E_SZ 256
#define V_SZ 512
#define T_MAX 16
#define PADM 129   // float2 per kk row (128+1) -> word stride 258 ≡ 2 (mod 32), conflict-free

// ---------------- persistent scratch ----------------
__device__ float g_h[B_SZ * E_SZ];
__device__ float g_gates[B_SZ * 1024];   // [ r(256) | z(256) | i_n(256) | h_n(256) ]
__device__ float g_logits[B_SZ * V_SZ];
__device__ int   g_tok[B_SZ];
__device__ int   g_alive[B_SZ];
__device__ int   g_N[B_SZ];
__device__ float g_logp[B_SZ];

// ---------------- helpers ----------------
__device__ __forceinline__ void fma2(ull &acc, ull a, ull b) {
    asm("fma.rn.f32x2 %0, %1, %2, %0;" : "+l"(acc) : "l"(a), "l"(b));
}
__device__ __forceinline__ void lds_1(ull &x, const float2 *p) {     // 8B-aligned OK
    u32 a = (u32)__cvta_generic_to_shared(p);
    asm volatile("ld.shared.b64 %0, [%1];" : "=l"(x) : "r"(a));
}
__device__ __forceinline__ float2 unpack2(ull v) {
    float2 r;
    asm("mov.b64 {%0,%1}, %2;" : "=f"(r.x), "=f"(r.y) : "l"(v));
    return r;
}

// ---------------- init ----------------
__global__ void __launch_bounds__(256) init_k(const int *__restrict__ actions,
                                              const float *__restrict__ h1) {
    int idx = blockIdx.x * 256 + threadIdx.x;
    int b = idx >> 8, j = idx & 255;
    g_h[idx] = h1[actions[b] * 256 + j];
    if (idx < B_SZ) {
        g_tok[idx] = 0; g_alive[idx] = 1; g_N[idx] = T_MAX; g_logp[idx] = 0.0f;
    }
}

// ---------------- GEMM: 128x128 block tile, 8x8 per-thread, BK=32 (f32x2 along K) ----
// kind==0 (gates), grid (128, 8):
//   by<4:   rz,  out cols [0,512),    K=512 concat[x|h], W=[W_ih|W_hh] rows by*128..
//   by=4,5: i_n, out cols [512,768),  K=256 (x), W_ih rows 512+..
//   by=6,7: h_n, out cols [768,1024), K=256 (h), W_hh rows 512+..
// kind==1 (logits), grid (128, 4): K=256 (h), W_out
__global__ void __launch_bounds__(256, 1) gemm_k(
    const float *__restrict__ d2e, const float *__restrict__ Wih,
    const float *__restrict__ Whh, const float *__restrict__ Wout,
    const float *__restrict__ bih, const float *__restrict__ bhh,
    const float *__restrict__ bout, int kind)
{
    __shared__ __align__(16) float2 As[16 * PADM];
    __shared__ __align__(16) float2 Ws[16 * PADM];
    __shared__ int stok[128];

    const int m0 = blockIdx.x * 128;
    const int by = blockIdx.y;
    const int tid = threadIdx.x;

    int wbase, ocbase, K, ow, asrc;
    float *outp;
    if (kind == 0) {
        ow = 1024; outp = g_gates;
        if (by < 4)       { asrc = 0; wbase = by * 128;             ocbase = wbase;       K = 512; }
        else if (by < 6)  { asrc = 1; wbase = 512 + (by - 4) * 128; ocbase = wbase;       K = 256; }
        else              { asrc = 2; wbase = 512 + (by - 6) * 128; ocbase = 256 + wbase; K = 256; }
    } else {
        ow = V_SZ; outp = g_logits; asrc = 2; wbase = by * 128; ocbase = wbase; K = 256;
    }

    if (asrc <= 1 && tid < 128) stok[tid] = g_tok[m0 + tid];
    __syncthreads();

    const int wid = tid >> 5, lane = tid & 31;
    const int ty = ((wid & 3) << 2) | (lane >> 3);   // 0..15 (4 distinct per warp; 8-lane broadcast reads)
    const int tx = ((wid >> 2) << 3) | (lane & 7);   // 0..15 (8 distinct per warp; conflict-free reads)

    ull acc[64];
#pragma unroll
    for (int i = 0; i < 64; i++) acc[i] = 0ull;

    for (int kt = 0; kt < K; kt += 32) {
        const bool ax   = (asrc == 1) || (asrc == 0 && kt < 256);
        const int  koff = (asrc == 0 && kt >= 256) ? (kt - 256) : kt;
        const float *Wp;
        if (kind == 1)       Wp = Wout;
        else if (asrc == 1)  Wp = Wih;
        else if (asrc == 2)  Wp = Whh;
        else                 Wp = (kt < 256) ? Wih : Whh;

        // global -> smem transpose: e -> (kk=e&15, m=e>>4); k-consecutive lanes (coalesced LDG);
        // STS word stride 258 ≡ 2 (mod 32) -> conflict-free
#pragma unroll
        for (int r = 0; r < 8; r++) {
            int e = tid + r * 256;
            int m = e >> 4, kk = e & 15;
            int k = koff + 2 * kk;
            float2 va;
            if (ax) va = *(const float2 *)(d2e + stok[m] * 256 + k);
            else    va = *(const float2 *)(g_h + (m0 + m) * 256 + k);
            As[kk * PADM + m] = va;
            Ws[kk * PADM + m] = *(const float2 *)(Wp + (wbase + m) * 256 + k);
        }
        __syncthreads();

#pragma unroll
        for (int kk = 0; kk < 16; kk++) {
            ull a[8];
#pragma unroll
            for (int i = 0; i < 8; i++)
                lds_1(a[i], &As[kk * PADM + ty * 8 + i]);    // 8B loads: alignment-safe, broadcast
#pragma unroll
            for (int j = 0; j < 8; j++) {
                ull w;
                lds_1(w, &Ws[kk * PADM + tx + 16 * j]);      // 8 distinct even banks per phase
                fma2(acc[0  + j], a[0], w);
                fma2(acc[8  + j], a[1], w);
                fma2(acc[16 + j], a[2], w);
                fma2(acc[24 + j], a[3], w);
                fma2(acc[32 + j], a[4], w);
                fma2(acc[40 + j], a[5], w);
                fma2(acc[48 + j], a[6], w);
                fma2(acc[56 + j], a[7], w);
            }
        }
        __syncthreads();
    }

    // epilogue: pairwise horizontal add + bias; cols n = tx + 16j (8-lane-consecutive 32B stores)
#pragma unroll
    for (int i = 0; i < 8; i++) {
        int row = m0 + ty * 8 + i;
#pragma unroll
        for (int j = 0; j < 8; j++) {
            int n = tx + 16 * j;
            float2 s = unpack2(acc[i * 8 + j]);
            float bb;
            if (kind == 1)    bb = bout[wbase + n];
            else if (by < 4)  bb = bih[ocbase + n] + bhh[ocbase + n];
            else if (by < 6)  bb = bih[wbase + n];
            else              bb = bhh[wbase + n];
            outp[row * ow + ocbase + n] = s.x + s.y + bb;
        }
    }
}

// ---------------- pointwise GRU combine ----------------
__global__ void __launch_bounds__(256) gru_k() {
    int idx = blockIdx.x * 256 + threadIdx.x;
    const float *g = g_gates + (idx >> 8) * 1024;
    int j = idx & 255;
    float pr = g[j], pz = g[256 + j], pn = g[512 + j], hn = g[768 + j];
    float r = 0.5f + 0.5f * tanhf(0.5f * pr);
    float z = 0.5f + 0.5f * tanhf(0.5f * pz);
    float n = tanhf(fmaf(r, hn, pn));
    float h = g_h[idx];
    g_h[idx] = (1.0f - z) * n + z * h;
}

// ---------------- threefry2x32 bits (ctr=(0,c), out = x0^x1) ----------------
__device__ __forceinline__ u32 tf_bits(u32 k0, u32 k1, u32 ctr) {
    u32 ks2 = k0 ^ k1 ^ 0x1BD11BDAu;
    u32 x0 = k0;
    u32 x1 = ctr + k1;
#define TFR(r) { x0 += x1; x1 = __funnelshift_l(x1, x1, r); x1 ^= x0; }
    TFR(13) TFR(15) TFR(26) TFR(6)
    x0 += k1;  x1 += ks2 + 1u;
    TFR(17) TFR(29) TFR(16) TFR(24)
    x0 += ks2; x1 += k0 + 2u;
    TFR(13) TFR(15) TFR(26) TFR(6)
    x0 += k0;  x1 += k1 + 3u;
    TFR(17) TFR(29) TFR(16) TFR(24)
    x0 += k1;  x1 += ks2 + 4u;
    TFR(13) TFR(15) TFR(26) TFR(6)
    x0 += ks2; x1 += k0 + 5u;
#undef TFR
    return x0 ^ x1;
}

// ---------------- sampler: one warp per row ----------------
__global__ void __launch_bounds__(256) sample_k(float *__restrict__ d_out,
                                                int t, u32 k0, u32 k1) {
    int row  = blockIdx.x * 8 + (threadIdx.x >> 5);
    int lane = threadIdx.x & 31;
    const float *lrow = g_logits + row * V_SZ;
    u32 cbase = (u32)row * V_SZ + (u32)lane;

    float best = -1e38f, blog = 0.0f, mx = -1e38f;
    int bidx = 0;
#pragma unroll 1
    for (int c = 0; c < 16; c++) {
        int v = lane + 32 * c;
        float lg = lrow[v];
        mx = fmaxf(mx, lg);
        u32 bits = tf_bits(k0, k1, cbase + 32u * c);
        float fl = __uint_as_float((bits >> 9) | 0x3f800000u) - 1.0f;
        float u  = fl + 1.17549435e-38f;
        float gv = -logf(-logf(u));
        float s  = gv + lg;
        if (s > best) { best = s; bidx = v; blog = lg; }
    }
    for (int o = 16; o; o >>= 1) mx = fmaxf(mx, __shfl_xor_sync(0xffffffffu, mx, o));
    float se = 0.0f;
#pragma unroll 1
    for (int c = 0; c < 16; c++) se += expf(lrow[lane + 32 * c] - mx);
    for (int o = 16; o; o >>= 1) se += __shfl_xor_sync(0xffffffffu, se, o);
    for (int o = 16; o; o >>= 1) {
        float s2 = __shfl_xor_sync(0xffffffffu, best, o);
        int   i2 = __shfl_xor_sync(0xffffffffu, bidx, o);
        float l2 = __shfl_xor_sync(0xffffffffu, blog, o);
        if (s2 > best || (s2 == best && i2 < bidx)) { best = s2; bidx = i2; blog = l2; }
    }
    if (lane == 0) {
        int alive = g_alive[row];
        float lp = (blog - mx) - logf(se);
        float logp = g_logp[row] + (alive ? lp : 0.0f);
        int tok = alive ? bidx : 0;
        if (alive && tok == 0) g_N[row] = t + 1;
        g_alive[row] = (alive && tok != 0) ? 1 : 0;
        g_logp[row]  = logp;
        g_tok[row]   = tok;
        d_out[row * T_MAX + t] = (float)tok;
        if (t == T_MAX - 1) {
            d_out[B_SZ * T_MAX + row]       = (float)g_N[row];
            d_out[B_SZ * (T_MAX + 1) + row] = logp;
        }
    }
}

// ---------------- host threefry ----------------
static void host_tf(u32 k0, u32 k1, u32 c0, u32 c1, u32 &o0, u32 &o1) {
    u32 ks2 = k0 ^ k1 ^ 0x1BD11BDAu;
    u32 x0 = c0 + k0, x1 = c1 + k1;
#define HR(r) { x0 += x1; x1 = (x1 << (r)) | (x1 >> (32 - (r))); x1 ^= x0; }
    HR(13) HR(15) HR(26) HR(6)
    x0 += k1;  x1 += ks2 + 1u;
    HR(17) HR(29) HR(16) HR(24)
    x0 += ks2; x1 += k0 + 2u;
    HR(13) HR(15) HR(26) HR(6)
    x0 += k0;  x1 += k1 + 3u;
    HR(17) HR(29) HR(16) HR(24)
    x0 += k1;  x1 += ks2 + 4u;
    HR(13) HR(15) HR(26) HR(6)
    x0 += ks2; x1 += k0 + 5u;
#undef HR
    o0 = x0; o1 = x1;
}

extern "C" void kernel_launch(void* const* d_in, const int* in_sizes, int n_in,
                              void* d_out, int out_size) {
    (void)in_sizes; (void)n_in; (void)out_size;
    const int*   actions = (const int*)  d_in[0];
    const float* h1      = (const float*)d_in[2];
    const float* d2e     = (const float*)d_in[3];
    const float* Wih     = (const float*)d_in[4];
    const float* Whh     = (const float*)d_in[5];
    const float* bih     = (const float*)d_in[6];
    const float* bhh     = (const float*)d_in[7];
    const float* Wout    = (const float*)d_in[8];
    const float* bout    = (const float*)d_in[9];
    float* out = (float*)d_out;

    u32 ks0[T_MAX], ks1[T_MAX];
    for (int t = 0; t < T_MAX; t++) host_tf(0u, 42u, 0u, (u32)t, ks0[t], ks1[t]);

    init_k<<<(B_SZ * E_SZ) / 256, 256>>>(actions, h1);
    for (int t = 0; t < T_MAX; t++) {
        gemm_k<<<dim3(B_SZ / 128, 8), 256>>>(d2e, Wih, Whh, Wout, bih, bhh, bout, 0);
        gru_k<<<(B_SZ * E_SZ) / 256, 256>>>();
        gemm_k<<<dim3(B_SZ / 128, 4), 256>>>(d2e, Wih, Whh, Wout, bih, bhh, bout, 1);
        sample_k<<<B_SZ / 8, 256>>>(out, t, ks0[t], ks1[t]);
    }
}